// round 4
// baseline (speedup 1.0000x reference)
#include <cuda_runtime.h>
#include <cuda_bf16.h>
#include <cstdint>

// Problem constants (from reference)
#define NN 50000   // nodes
#define MM 10000   // hyperedges (static segment count)
#define DD 128     // feature dim

// ---------------- static scratch (no allocations allowed) ----------------
__device__ float g_esum [MM * DD];   // seg_sum of raw x over edges   5.1 MB
__device__ float g_eproj[MM * DD];   // (esum/cnt) @ Wveu             5.1 MB
__device__ float g_nsum [NN * DD];   // node sums (output space)     25.6 MB
__device__ float g_wvu  [DD * DD];   // W_v @ W_u_top
__device__ float g_wve  [DD * DD];   // W_v @ W_e
__device__ float g_wveu [DD * DD];   // W_v @ W_e @ W_u_bot
__device__ int   g_ecnt [MM];
__device__ int   g_ncnt [NN];
__device__ int   g_colmin;

// ---------------- init: zero accumulators, reset colmin ----------------
__global__ void k_init() {
    int i = blockIdx.x * blockDim.x + threadIdx.x;
    int stride = gridDim.x * blockDim.x;
    for (int j = i; j < NN * DD; j += stride) g_nsum[j] = 0.0f;
    for (int j = i; j < MM * DD; j += stride) g_esum[j] = 0.0f;
    for (int j = i; j < NN; j += stride) g_ncnt[j] = 0;
    for (int j = i; j < MM; j += stride) g_ecnt[j] = 0;
    if (i == 0) g_colmin = 0x7fffffff;
}

// ---------------- col min reduction ----------------
__global__ void k_colmin(const int* __restrict__ col, int E) {
    int v = 0x7fffffff;
    for (int j = blockIdx.x * blockDim.x + threadIdx.x; j < E;
         j += gridDim.x * blockDim.x)
        v = min(v, col[j]);
#pragma unroll
    for (int o = 16; o > 0; o >>= 1) v = min(v, __shfl_down_sync(0xffffffffu, v, o));
    if ((threadIdx.x & 31) == 0) atomicMin(&g_colmin, v);
}

// ---------------- vector float atomic add (sm_90+) ----------------
__device__ __forceinline__ void red_add_v4(float* p, float4 v) {
    asm volatile("red.global.add.v4.f32 [%0], {%1,%2,%3,%4};"
                 :: "l"(p), "f"(v.x), "f"(v.y), "f"(v.z), "f"(v.w)
                 : "memory");
}

// ---------------- scatter 1: raw node features -> hyperedge sums ----------------
__global__ void k_scatter1(const float* __restrict__ x,
                           const int* __restrict__ row, const int* __restrict__ col, int E) {
    const int cmin = g_colmin;
    const int lane = threadIdx.x & 31;
    const int warp = (blockIdx.x * blockDim.x + threadIdx.x) >> 5;
    const int nw   = (gridDim.x * blockDim.x) >> 5;
    for (int e = warp; e < E; e += nw) {
        int r = __ldg(&row[e]);
        int c = __ldg(&col[e]) - cmin;
        float4 v = *(const float4*)&x[(size_t)r * DD + lane * 4];
        red_add_v4(&g_esum[(size_t)c * DD + lane * 4], v);
        if (lane == 0) atomicAdd(&g_ecnt[c], 1);
    }
}

// ---------------- scatter 2: hyperedge features (output space) -> node sums ----------------
__global__ void k_scatter2(const int* __restrict__ row, const int* __restrict__ col, int E) {
    const int cmin = g_colmin;
    const int lane = threadIdx.x & 31;
    const int warp = (blockIdx.x * blockDim.x + threadIdx.x) >> 5;
    const int nw   = (gridDim.x * blockDim.x) >> 5;
    for (int e = warp; e < E; e += nw) {
        int r = __ldg(&row[e]);
        int c = __ldg(&col[e]) - cmin;
        float4 v = *(const float4*)&g_eproj[(size_t)c * DD + lane * 4];
        red_add_v4(&g_nsum[(size_t)r * DD + lane * 4], v);
        if (lane == 0) atomicAdd(&g_ncnt[r], 1);
    }
}

// ---------------- double-buffered SGEMM body: C = A[Mrows x 128] @ B[128 x 128] ----------------
// SCALE0: A rows scaled by 1/max(cnt0[row],1) (segment-mean fold, hoisted out of k-loop)
// FINAL:  C = relu(acc + nsum[row]/max(ncnt[row],1) + bias)
template <bool SCALE0, bool FINAL>
__device__ __forceinline__ void gemm_body(
    const float* __restrict__ A0, const int* __restrict__ cnt0,
    const float* __restrict__ Bm, const float* __restrict__ bias,
    float* __restrict__ C, int Mrows)
{
    __shared__ float As[2][16][132];
    __shared__ float Bs[2][16][128];

    const int tid = threadIdx.x;
    const int ty = tid >> 4;   // 0..15
    const int tx = tid & 15;   // 0..15
    const int rowBase = blockIdx.x * 128;

    const int aRow = tid >> 2;        // 0..63
    const int aCol = (tid & 3) << 2;  // 0,4,8,12
    const int bRow = tid >> 5;        // 0..7
    const int bCol = (tid & 31) << 2; // 0..124

    float scl[2] = {1.0f, 1.0f};
    if (SCALE0) {
#pragma unroll
        for (int p = 0; p < 2; p++) {
            int gr = rowBase + aRow + p * 64;
            if (gr < Mrows) scl[p] = 1.0f / fmaxf((float)__ldg(&cnt0[gr]), 1.0f);
        }
    }

    float acc[8][8];
#pragma unroll
    for (int i = 0; i < 8; i++)
#pragma unroll
        for (int j = 0; j < 8; j++) acc[i][j] = 0.0f;

    float4 pa[2], pb[2];
    // prefetch k-tile 0
#pragma unroll
    for (int p = 0; p < 2; p++) {
        int gr = rowBase + aRow + p * 64;
        pa[p] = make_float4(0.f, 0.f, 0.f, 0.f);
        if (gr < Mrows) {
            pa[p] = *(const float4*)&A0[(size_t)gr * DD + aCol];
            if (SCALE0) { pa[p].x *= scl[p]; pa[p].y *= scl[p]; pa[p].z *= scl[p]; pa[p].w *= scl[p]; }
        }
        pb[p] = *(const float4*)&Bm[(size_t)(bRow + p * 8) * DD + bCol];
    }
#pragma unroll
    for (int p = 0; p < 2; p++) {
        int r = aRow + p * 64;
        As[0][aCol + 0][r] = pa[p].x;
        As[0][aCol + 1][r] = pa[p].y;
        As[0][aCol + 2][r] = pa[p].z;
        As[0][aCol + 3][r] = pa[p].w;
        *(float4*)&Bs[0][bRow + p * 8][bCol] = pb[p];
    }
    __syncthreads();

#pragma unroll
    for (int kb = 0; kb < 8; kb++) {
        // prefetch next tile into registers (overlaps with compute below)
        if (kb < 7) {
            const int ko = (kb + 1) * 16;
#pragma unroll
            for (int p = 0; p < 2; p++) {
                int gr = rowBase + aRow + p * 64;
                pa[p] = make_float4(0.f, 0.f, 0.f, 0.f);
                if (gr < Mrows) {
                    pa[p] = *(const float4*)&A0[(size_t)gr * DD + ko + aCol];
                    if (SCALE0) { pa[p].x *= scl[p]; pa[p].y *= scl[p]; pa[p].z *= scl[p]; pa[p].w *= scl[p]; }
                }
                pb[p] = *(const float4*)&Bm[(size_t)(ko + bRow + p * 8) * DD + bCol];
            }
        }
        const int cb = kb & 1;
#pragma unroll
        for (int k = 0; k < 16; k++) {
            float ar[8], br[8];
            *(float4*)&ar[0] = *(const float4*)&As[cb][k][ty * 8];
            *(float4*)&ar[4] = *(const float4*)&As[cb][k][ty * 8 + 4];
            *(float4*)&br[0] = *(const float4*)&Bs[cb][k][tx * 8];
            *(float4*)&br[4] = *(const float4*)&Bs[cb][k][tx * 8 + 4];
#pragma unroll
            for (int i = 0; i < 8; i++)
#pragma unroll
                for (int j = 0; j < 8; j++)
                    acc[i][j] = fmaf(ar[i], br[j], acc[i][j]);
        }
        if (kb < 7) {
            const int nb = cb ^ 1;
#pragma unroll
            for (int p = 0; p < 2; p++) {
                int r = aRow + p * 64;
                As[nb][aCol + 0][r] = pa[p].x;
                As[nb][aCol + 1][r] = pa[p].y;
                As[nb][aCol + 2][r] = pa[p].z;
                As[nb][aCol + 3][r] = pa[p].w;
                *(float4*)&Bs[nb][bRow + p * 8][bCol] = pb[p];
            }
            __syncthreads();
        }
    }

    // epilogue
#pragma unroll
    for (int i = 0; i < 8; i++) {
        int gr = rowBase + ty * 8 + i;
        if (gr >= Mrows) continue;
        float inv = 1.0f;
        if (FINAL) inv = 1.0f / fmaxf((float)__ldg(&g_ncnt[gr]), 1.0f);
#pragma unroll
        for (int j = 0; j < 8; j += 4) {
            int gc = tx * 8 + j;
            float4 v = make_float4(acc[i][j], acc[i][j + 1], acc[i][j + 2], acc[i][j + 3]);
            if (FINAL) {
                float4 s = *(const float4*)&g_nsum[(size_t)gr * DD + gc];
                v.x = fmaxf(fmaf(s.x, inv, v.x) + __ldg(&bias[gc + 0]), 0.0f);
                v.y = fmaxf(fmaf(s.y, inv, v.y) + __ldg(&bias[gc + 1]), 0.0f);
                v.z = fmaxf(fmaf(s.z, inv, v.z) + __ldg(&bias[gc + 2]), 0.0f);
                v.w = fmaxf(fmaf(s.w, inv, v.w) + __ldg(&bias[gc + 3]), 0.0f);
            }
            *(float4*)&C[(size_t)gr * DD + gc] = v;
        }
    }
}

// Dual GEMM: blockIdx.y selects config
__global__ void __launch_bounds__(256, 2) k_gemm_dual(
    const float* Aa, const float* Ba, float* Ca,
    const float* Ab, const float* Bb, float* Cb, int Mrows)
{
    if (blockIdx.y == 0) gemm_body<false, false>(Aa, nullptr, Ba, nullptr, Ca, Mrows);
    else                 gemm_body<false, false>(Ab, nullptr, Bb, nullptr, Cb, Mrows);
}

// Plain single GEMM
__global__ void __launch_bounds__(256, 2) k_gemm_plain(
    const float* A, const float* B, float* C, int Mrows)
{
    gemm_body<false, false>(A, nullptr, B, nullptr, C, Mrows);
}

// Scaled GEMM (segment mean folded into A loads)
__global__ void __launch_bounds__(256, 2) k_gemm_scale(
    const float* A, const int* cnt, const float* B, float* C, int Mrows)
{
    gemm_body<true, false>(A, cnt, B, nullptr, C, Mrows);
}

// Final GEMM with fused epilogue: out = relu(x@Wvu + nsum/ncnt + bias)
__global__ void __launch_bounds__(256, 2) k_gemm_final(
    const float* A, const float* B, const float* bias, float* C, int Mrows)
{
    gemm_body<false, true>(A, nullptr, B, bias, C, Mrows);
}

// ---------------- launch ----------------
extern "C" void kernel_launch(void* const* d_in, const int* in_sizes, int n_in,
                              void* d_out, int out_size)
{
    const float* x   = (const float*)d_in[0];   // (N, 128)
    const int*   ei  = (const int*)  d_in[1];   // (2, E): row then col
    const float* Wv  = (const float*)d_in[2];   // (128, 128)
    const float* We  = (const float*)d_in[3];   // (128, 128)
    const float* Wu  = (const float*)d_in[4];   // (256, 128)
    const float* bu  = (const float*)d_in[5];   // (128,)
    float* out = (float*)d_out;                 // (N, 128)

    const int E = in_sizes[1] / 2;
    const int N = in_sizes[0] / DD;
    const int* rowp = ei;
    const int* colp = ei + E;

    float* esum;  cudaGetSymbolAddress((void**)&esum,  g_esum);
    float* eproj; cudaGetSymbolAddress((void**)&eproj, g_eproj);
    float* wvu;   cudaGetSymbolAddress((void**)&wvu,   g_wvu);
    float* wve;   cudaGetSymbolAddress((void**)&wve,   g_wve);
    float* wveu;  cudaGetSymbolAddress((void**)&wveu,  g_wveu);
    int* ecnt;    cudaGetSymbolAddress((void**)&ecnt,  g_ecnt);

    // 1. init accumulators + colmin
    k_init<<<512, 256>>>();
    k_colmin<<<512, 256>>>(colp, E);
    // 2. scatter raw node features -> hyperedge sums (independent of all GEMMs)
    k_scatter1<<<4096, 256>>>(x, rowp, colp, E);
    // 3. weight combos: Wvu = Wv@Wu_top ; Wve = Wv@We ; Wveu = Wve@Wu_bot
    {
        dim3 g(1, 2);
        k_gemm_dual<<<g, 256>>>(Wv, Wu, wvu, Wv, We, wve, DD);
    }
    k_gemm_plain<<<1, 256>>>(wve, Wu + DD * DD, wveu, DD);
    // 4. eproj = (esum/ecnt) @ Wveu   (directly in output space)
    k_gemm_scale<<<(MM + 127) / 128, 256>>>(esum, ecnt, wveu, eproj, MM);
    // 5. scatter hyperedge features -> node sums
    k_scatter2<<<4096, 256>>>(rowp, colp, E);
    // 6. out = relu(x@Wvu + nsum/ncnt + bias)   (fused final)
    k_gemm_final<<<(N + 127) / 128, 256>>>(x, wvu, bu, out, N);
}

// round 5
// speedup vs baseline: 1.5258x; 1.5258x over previous
#include <cuda_runtime.h>
#include <cuda_bf16.h>
#include <cstdint>

// Problem constants (from reference)
#define NN 50000   // nodes
#define MM 10000   // hyperedges (static segment count)
#define DD 128     // feature dim

// ---------------- static scratch (no allocations allowed) ----------------
__device__ float g_esum [MM * DD];   // seg_sum of raw x over edges   5.1 MB
__device__ float g_eproj[MM * DD];   // (esum/cnt) @ Wveu             5.1 MB
__device__ float g_nsum [NN * DD];   // node sums (output space)     25.6 MB
__device__ float g_wvu  [DD * DD];   // W_v @ W_u_top
__device__ float g_wveu [DD * DD];   // W_v @ W_e @ W_u_bot
__device__ int   g_ecnt [MM];
__device__ int   g_ncnt [NN];
__device__ int   g_colmin;

// ---------------- init: zero accumulators (vectorized), reset colmin ----------------
__global__ void k_init() {
    int i = blockIdx.x * blockDim.x + threadIdx.x;
    int stride = gridDim.x * blockDim.x;
    float4 z = make_float4(0.f, 0.f, 0.f, 0.f);
    for (int j = i; j < NN * DD / 4; j += stride) ((float4*)g_nsum)[j] = z;
    for (int j = i; j < MM * DD / 4; j += stride) ((float4*)g_esum)[j] = z;
    for (int j = i; j < NN; j += stride) g_ncnt[j] = 0;
    for (int j = i; j < MM; j += stride) g_ecnt[j] = 0;
    if (i == 0) g_colmin = 0x7fffffff;
}

// ---------------- col min reduction ----------------
__global__ void k_colmin(const int* __restrict__ col, int E) {
    int v = 0x7fffffff;
    for (int j = blockIdx.x * blockDim.x + threadIdx.x; j < E;
         j += gridDim.x * blockDim.x)
        v = min(v, col[j]);
#pragma unroll
    for (int o = 16; o > 0; o >>= 1) v = min(v, __shfl_down_sync(0xffffffffu, v, o));
    if ((threadIdx.x & 31) == 0) atomicMin(&g_colmin, v);
}

// ---------------- weight combos: Wvu = Wv@Wu_top ; Wveu = Wv@We@Wu_bot ----------------
// grid = 256 blocks x 128 threads; one block per output row.
__global__ void __launch_bounds__(128) k_combo(
    const float* __restrict__ Wv, const float* __restrict__ We,
    const float* __restrict__ Wu)
{
    __shared__ float rowv[DD];
    __shared__ float tmp[DD];
    const int c = threadIdx.x;
    const int b = blockIdx.x;
    const float* Wu_top = Wu;
    const float* Wu_bot = Wu + DD * DD;

    if (b < DD) {
        const int r = b;
        rowv[c] = Wv[r * DD + c];
        __syncthreads();
        float a0 = 0.f, a1 = 0.f;
#pragma unroll
        for (int k = 0; k < DD; k += 2) {
            a0 = fmaf(rowv[k],     Wu_top[(k)     * DD + c], a0);
            a1 = fmaf(rowv[k + 1], Wu_top[(k + 1) * DD + c], a1);
        }
        g_wvu[r * DD + c] = a0 + a1;
    } else {
        const int r = b - DD;
        rowv[c] = Wv[r * DD + c];
        __syncthreads();
        float a0 = 0.f, a1 = 0.f;
#pragma unroll
        for (int k = 0; k < DD; k += 2) {
            a0 = fmaf(rowv[k],     We[(k)     * DD + c], a0);
            a1 = fmaf(rowv[k + 1], We[(k + 1) * DD + c], a1);
        }
        tmp[c] = a0 + a1;
        __syncthreads();
        float b0 = 0.f, b1 = 0.f;
#pragma unroll
        for (int k = 0; k < DD; k += 2) {
            b0 = fmaf(tmp[k],     Wu_bot[(k)     * DD + c], b0);
            b1 = fmaf(tmp[k + 1], Wu_bot[(k + 1) * DD + c], b1);
        }
        g_wveu[r * DD + c] = b0 + b1;
    }
}

// ---------------- vector float atomic add (sm_90+) ----------------
__device__ __forceinline__ void red_add_v4(float* p, float4 v) {
    asm volatile("red.global.add.v4.f32 [%0], {%1,%2,%3,%4};"
                 :: "l"(p), "f"(v.x), "f"(v.y), "f"(v.z), "f"(v.w)
                 : "memory");
}

// ---------------- scatter 1: raw node features -> hyperedge sums ----------------
__global__ void k_scatter1(const float* __restrict__ x,
                           const int* __restrict__ row, const int* __restrict__ col, int E) {
    const int cmin = g_colmin;
    const int lane = threadIdx.x & 31;
    const int warp = (blockIdx.x * blockDim.x + threadIdx.x) >> 5;
    const int nw   = (gridDim.x * blockDim.x) >> 5;
    for (int e = warp; e < E; e += nw) {
        int r = __ldg(&row[e]);
        int c = __ldg(&col[e]) - cmin;
        float4 v = *(const float4*)&x[(size_t)r * DD + lane * 4];
        red_add_v4(&g_esum[(size_t)c * DD + lane * 4], v);
        if (lane == 0) atomicAdd(&g_ecnt[c], 1);
    }
}

// ---------------- scatter 2: hyperedge features (output space) -> node sums ----------------
__global__ void k_scatter2(const int* __restrict__ row, const int* __restrict__ col, int E) {
    const int cmin = g_colmin;
    const int lane = threadIdx.x & 31;
    const int warp = (blockIdx.x * blockDim.x + threadIdx.x) >> 5;
    const int nw   = (gridDim.x * blockDim.x) >> 5;
    for (int e = warp; e < E; e += nw) {
        int r = __ldg(&row[e]);
        int c = __ldg(&col[e]) - cmin;
        float4 v = *(const float4*)&g_eproj[(size_t)c * DD + lane * 4];
        red_add_v4(&g_nsum[(size_t)r * DD + lane * 4], v);
        if (lane == 0) atomicAdd(&g_ncnt[r], 1);
    }
}

// ---------------- double-buffered SGEMM body: C = A[Mrows x 128] @ B[128 x 128] ----------------
// SCALE0: A rows scaled by 1/max(cnt0[row],1) (segment-mean fold, hoisted out of k-loop)
// FINAL:  C = relu(acc + nsum[row]/max(ncnt[row],1) + bias)
template <bool SCALE0, bool FINAL>
__device__ __forceinline__ void gemm_body(
    const float* __restrict__ A0, const int* __restrict__ cnt0,
    const float* __restrict__ Bm, const float* __restrict__ bias,
    float* __restrict__ C, int Mrows)
{
    __shared__ float As[2][16][132];
    __shared__ float Bs[2][16][128];

    const int tid = threadIdx.x;
    const int ty = tid >> 4;   // 0..15
    const int tx = tid & 15;   // 0..15
    const int rowBase = blockIdx.x * 128;

    const int aRow = tid >> 2;        // 0..63
    const int aCol = (tid & 3) << 2;  // 0,4,8,12
    const int bRow = tid >> 5;        // 0..7
    const int bCol = (tid & 31) << 2; // 0..124

    float scl[2] = {1.0f, 1.0f};
    if (SCALE0) {
#pragma unroll
        for (int p = 0; p < 2; p++) {
            int gr = rowBase + aRow + p * 64;
            if (gr < Mrows) scl[p] = 1.0f / fmaxf((float)__ldg(&cnt0[gr]), 1.0f);
        }
    }

    float acc[8][8];
#pragma unroll
    for (int i = 0; i < 8; i++)
#pragma unroll
        for (int j = 0; j < 8; j++) acc[i][j] = 0.0f;

    float4 pa[2], pb[2];
    // prefetch k-tile 0
#pragma unroll
    for (int p = 0; p < 2; p++) {
        int gr = rowBase + aRow + p * 64;
        pa[p] = make_float4(0.f, 0.f, 0.f, 0.f);
        if (gr < Mrows) {
            pa[p] = *(const float4*)&A0[(size_t)gr * DD + aCol];
            if (SCALE0) { pa[p].x *= scl[p]; pa[p].y *= scl[p]; pa[p].z *= scl[p]; pa[p].w *= scl[p]; }
        }
        pb[p] = *(const float4*)&Bm[(size_t)(bRow + p * 8) * DD + bCol];
    }
#pragma unroll
    for (int p = 0; p < 2; p++) {
        int r = aRow + p * 64;
        As[0][aCol + 0][r] = pa[p].x;
        As[0][aCol + 1][r] = pa[p].y;
        As[0][aCol + 2][r] = pa[p].z;
        As[0][aCol + 3][r] = pa[p].w;
        *(float4*)&Bs[0][bRow + p * 8][bCol] = pb[p];
    }
    __syncthreads();

#pragma unroll
    for (int kb = 0; kb < 8; kb++) {
        // prefetch next tile into registers (overlaps with compute below)
        if (kb < 7) {
            const int ko = (kb + 1) * 16;
#pragma unroll
            for (int p = 0; p < 2; p++) {
                int gr = rowBase + aRow + p * 64;
                pa[p] = make_float4(0.f, 0.f, 0.f, 0.f);
                if (gr < Mrows) {
                    pa[p] = *(const float4*)&A0[(size_t)gr * DD + ko + aCol];
                    if (SCALE0) { pa[p].x *= scl[p]; pa[p].y *= scl[p]; pa[p].z *= scl[p]; pa[p].w *= scl[p]; }
                }
                pb[p] = *(const float4*)&Bm[(size_t)(ko + bRow + p * 8) * DD + bCol];
            }
        }
        const int cb = kb & 1;
#pragma unroll
        for (int k = 0; k < 16; k++) {
            float ar[8], br[8];
            *(float4*)&ar[0] = *(const float4*)&As[cb][k][ty * 8];
            *(float4*)&ar[4] = *(const float4*)&As[cb][k][ty * 8 + 4];
            *(float4*)&br[0] = *(const float4*)&Bs[cb][k][tx * 8];
            *(float4*)&br[4] = *(const float4*)&Bs[cb][k][tx * 8 + 4];
#pragma unroll
            for (int i = 0; i < 8; i++)
#pragma unroll
                for (int j = 0; j < 8; j++)
                    acc[i][j] = fmaf(ar[i], br[j], acc[i][j]);
        }
        if (kb < 7) {
            const int nb = cb ^ 1;
#pragma unroll
            for (int p = 0; p < 2; p++) {
                int r = aRow + p * 64;
                As[nb][aCol + 0][r] = pa[p].x;
                As[nb][aCol + 1][r] = pa[p].y;
                As[nb][aCol + 2][r] = pa[p].z;
                As[nb][aCol + 3][r] = pa[p].w;
                *(float4*)&Bs[nb][bRow + p * 8][bCol] = pb[p];
            }
            __syncthreads();
        }
    }

    // epilogue
#pragma unroll
    for (int i = 0; i < 8; i++) {
        int gr = rowBase + ty * 8 + i;
        if (gr >= Mrows) continue;
        float inv = 1.0f;
        if (FINAL) inv = 1.0f / fmaxf((float)__ldg(&g_ncnt[gr]), 1.0f);
#pragma unroll
        for (int j = 0; j < 8; j += 4) {
            int gc = tx * 8 + j;
            float4 v = make_float4(acc[i][j], acc[i][j + 1], acc[i][j + 2], acc[i][j + 3]);
            if (FINAL) {
                float4 s = *(const float4*)&g_nsum[(size_t)gr * DD + gc];
                v.x = fmaxf(fmaf(s.x, inv, v.x) + __ldg(&bias[gc + 0]), 0.0f);
                v.y = fmaxf(fmaf(s.y, inv, v.y) + __ldg(&bias[gc + 1]), 0.0f);
                v.z = fmaxf(fmaf(s.z, inv, v.z) + __ldg(&bias[gc + 2]), 0.0f);
                v.w = fmaxf(fmaf(s.w, inv, v.w) + __ldg(&bias[gc + 3]), 0.0f);
            }
            *(float4*)&C[(size_t)gr * DD + gc] = v;
        }
    }
}

// Scaled GEMM (segment mean folded into A loads)
__global__ void __launch_bounds__(256, 2) k_gemm_scale(
    const float* A, const int* cnt, const float* B, float* C, int Mrows)
{
    gemm_body<true, false>(A, cnt, B, nullptr, C, Mrows);
}

// Final GEMM with fused epilogue: out = relu(x@Wvu + nsum/ncnt + bias)
__global__ void __launch_bounds__(256, 2) k_gemm_final(
    const float* A, const float* B, const float* bias, float* C, int Mrows)
{
    gemm_body<false, true>(A, nullptr, B, bias, C, Mrows);
}

// ---------------- launch ----------------
extern "C" void kernel_launch(void* const* d_in, const int* in_sizes, int n_in,
                              void* d_out, int out_size)
{
    const float* x   = (const float*)d_in[0];   // (N, 128)
    const int*   ei  = (const int*)  d_in[1];   // (2, E): row then col
    const float* Wv  = (const float*)d_in[2];   // (128, 128)
    const float* We  = (const float*)d_in[3];   // (128, 128)
    const float* Wu  = (const float*)d_in[4];   // (256, 128)
    const float* bu  = (const float*)d_in[5];   // (128,)
    float* out = (float*)d_out;                 // (N, 128)

    const int E = in_sizes[1] / 2;
    const int N = in_sizes[0] / DD;
    const int* rowp = ei;
    const int* colp = ei + E;

    float* esum;  cudaGetSymbolAddress((void**)&esum,  g_esum);
    float* eproj; cudaGetSymbolAddress((void**)&eproj, g_eproj);
    float* wvu;   cudaGetSymbolAddress((void**)&wvu,   g_wvu);
    float* wveu;  cudaGetSymbolAddress((void**)&wveu,  g_wveu);
    int* ecnt;    cudaGetSymbolAddress((void**)&ecnt,  g_ecnt);

    // 1. init accumulators + colmin
    k_init<<<512, 256>>>();
    k_colmin<<<512, 256>>>(colp, E);
    // 2. weight combos (parallel, single launch): Wvu = Wv@Wu_top ; Wveu = Wv@We@Wu_bot
    k_combo<<<256, 128>>>(Wv, We, Wu);
    // 3. scatter raw node features -> hyperedge sums
    k_scatter1<<<4096, 256>>>(x, rowp, colp, E);
    // 4. eproj = (esum/ecnt) @ Wveu   (directly in output space)
    k_gemm_scale<<<(MM + 127) / 128, 256>>>(esum, ecnt, wveu, eproj, MM);
    // 5. scatter hyperedge features -> node sums
    k_scatter2<<<4096, 256>>>(rowp, colp, E);
    // 6. out = relu(x@Wvu + nsum/ncnt + bias)   (fused final)
    k_gemm_final<<<(N + 127) / 128, 256>>>(x, wvu, bu, out, N);
}